// round 2
// baseline (speedup 1.0000x reference)
#include <cuda_runtime.h>
#include <cstdint>

#define VOCAB  32000
#define EMBED  256
#define HIDDEN 512
#define BATCH  64
#define TCAP   32
#define SEQ    33                 // T_CAP + 1
#define MROWS  (SEQ*BATCH)        // 2112
#define G4     (4*HIDDEN)         // 2048
#define OUT_SV (SEQ*VOCAB)        // 1056000

// ---------------- scratch (static device globals; no allocation) -------------
__device__ float d_xg[MROWS*EMBED];        // gathered inputs  [s*64+b][256]
__device__ float d_xproj[MROWS*G4];        // x@W_ih^T + b     [s*64+b][2048]
__device__ float d_hs[MROWS*HIDDEN];       // hidden states    [s*64+b][512]
__device__ float d_c[BATCH*HIDDEN];        // cell state       [b][512]

// ---------------- helpers ----------------------------------------------------
__device__ __forceinline__ unsigned f2tf32(float x) {
    unsigned r;
    asm("cvt.rna.tf32.f32 %0, %1;" : "=r"(r) : "f"(x));
    return r;
}

__device__ __forceinline__ void mma_tf32(float c[4], const unsigned a[4], const unsigned b[2]) {
    asm volatile(
        "mma.sync.aligned.m16n8k8.row.col.f32.tf32.tf32.f32 "
        "{%0,%1,%2,%3},{%4,%5,%6,%7},{%8,%9},{%0,%1,%2,%3};\n"
        : "+f"(c[0]), "+f"(c[1]), "+f"(c[2]), "+f"(c[3])
        : "r"(a[0]), "r"(a[1]), "r"(a[2]), "r"(a[3]), "r"(b[0]), "r"(b[1]));
}

__device__ __forceinline__ float sigf(float x) { return 1.0f / (1.0f + expf(-x)); }

// ---------------- gather: build x rows (s-major) -----------------------------
__global__ void gather_kernel(const float* __restrict__ features,
                              const int*   __restrict__ captions,
                              const float* __restrict__ embedding) {
    int m = blockIdx.x;            // 0..2111
    int s = m >> 6, b = m & 63;
    const float* src = (s == 0) ? (features + (size_t)b * EMBED)
                                : (embedding + (size_t)captions[b * TCAP + (s - 1)] * EMBED);
    float* dst = d_xg + (size_t)m * EMBED;
    for (int i = threadIdx.x; i < EMBED; i += blockDim.x) dst[i] = src[i];
}

// ---------------- generic 128x128 tf32 GEMM: C = A[M,K] @ B[N,K]^T + bias ----
// mode 0: C[m*N+n] = acc + bias1[n] + bias2[n]          (x_proj)
// mode 1: out[b*OUT_SV + s*VOCAB + n] = acc + bias1[n]  (logits; m = s*64+b)
#define SROW 36
__global__ __launch_bounds__(256, 2)
void gemm128(const float* __restrict__ A, const float* __restrict__ B,
             const float* __restrict__ bias1, const float* __restrict__ bias2,
             float* __restrict__ C, int M, int N, int K, int mode) {
    __shared__ float sA[128 * SROW];
    __shared__ float sB[128 * SROW];

    const int m0 = blockIdx.y * 128, n0 = blockIdx.x * 128;
    const int tid  = threadIdx.x;
    const int warp = tid >> 5, lane = tid & 31;
    const int grp  = lane >> 2, tig = lane & 3;
    const int wm = warp & 1, wn = warp >> 1;       // 2 warps in M, 4 in N
    const int mb = wm * 64, nb = wn * 32;          // warp tile 64x32

    float acc[4][4][4];
    #pragma unroll
    for (int mt = 0; mt < 4; mt++)
        #pragma unroll
        for (int nt = 0; nt < 4; nt++)
            #pragma unroll
            for (int q = 0; q < 4; q++) acc[mt][nt][q] = 0.0f;

    for (int k0 = 0; k0 < K; k0 += 32) {
        // stage A and B tiles (128 x 32), converting to tf32
        #pragma unroll
        for (int i = 0; i < 4; i++) {
            int lin = tid + i * 256;               // 0..1023
            int r = lin >> 3;
            int c4 = (lin & 7) << 2;
            int gm = m0 + r;
            float4 va = (gm < M) ? *(const float4*)(A + (size_t)gm * K + k0 + c4)
                                 : make_float4(0.f, 0.f, 0.f, 0.f);
            float* da = sA + r * SROW + c4;
            da[0] = __uint_as_float(f2tf32(va.x));
            da[1] = __uint_as_float(f2tf32(va.y));
            da[2] = __uint_as_float(f2tf32(va.z));
            da[3] = __uint_as_float(f2tf32(va.w));
            float4 vb = *(const float4*)(B + (size_t)(n0 + r) * K + k0 + c4);
            float* db = sB + r * SROW + c4;
            db[0] = __uint_as_float(f2tf32(vb.x));
            db[1] = __uint_as_float(f2tf32(vb.y));
            db[2] = __uint_as_float(f2tf32(vb.z));
            db[3] = __uint_as_float(f2tf32(vb.w));
        }
        __syncthreads();

        #pragma unroll
        for (int ks = 0; ks < 32; ks += 8) {
            unsigned af[4][4];
            unsigned bf[4][2];
            #pragma unroll
            for (int mt = 0; mt < 4; mt++) {
                const float* base = sA + (mb + mt * 16) * SROW + ks;
                af[mt][0] = __float_as_uint(base[grp * SROW + tig]);
                af[mt][1] = __float_as_uint(base[(grp + 8) * SROW + tig]);
                af[mt][2] = __float_as_uint(base[grp * SROW + tig + 4]);
                af[mt][3] = __float_as_uint(base[(grp + 8) * SROW + tig + 4]);
            }
            #pragma unroll
            for (int nt = 0; nt < 4; nt++) {
                const float* base = sB + (nb + nt * 8 + grp) * SROW + ks;
                bf[nt][0] = __float_as_uint(base[tig]);
                bf[nt][1] = __float_as_uint(base[tig + 4]);
            }
            #pragma unroll
            for (int mt = 0; mt < 4; mt++)
                #pragma unroll
                for (int nt = 0; nt < 4; nt++)
                    mma_tf32(acc[mt][nt], af[mt], bf[nt]);
        }
        __syncthreads();
    }

    // epilogue
    #pragma unroll
    for (int mt = 0; mt < 4; mt++) {
        #pragma unroll
        for (int nt = 0; nt < 4; nt++) {
            int rA = m0 + mb + mt * 16 + grp;
            int rB = rA + 8;
            int n  = n0 + nb + nt * 8 + 2 * tig;
            float bv0 = bias1 ? bias1[n]     : 0.0f;
            float bv1 = bias1 ? bias1[n + 1] : 0.0f;
            if (bias2) { bv0 += bias2[n]; bv1 += bias2[n + 1]; }
            if (mode == 0) {
                if (rA < M) {
                    C[(size_t)rA * N + n]     = acc[mt][nt][0] + bv0;
                    C[(size_t)rA * N + n + 1] = acc[mt][nt][1] + bv1;
                }
                if (rB < M) {
                    C[(size_t)rB * N + n]     = acc[mt][nt][2] + bv0;
                    C[(size_t)rB * N + n + 1] = acc[mt][nt][3] + bv1;
                }
            } else {
                if (rA < M) {
                    int s = rA >> 6, b = rA & 63;
                    size_t o = (size_t)b * OUT_SV + (size_t)s * VOCAB + n;
                    C[o]     = acc[mt][nt][0] + bv0;
                    C[o + 1] = acc[mt][nt][1] + bv1;
                }
                if (rB < M) {
                    int s = rB >> 6, b = rB & 63;
                    size_t o = (size_t)b * OUT_SV + (size_t)s * VOCAB + n;
                    C[o]     = acc[mt][nt][2] + bv0;
                    C[o + 1] = acc[mt][nt][3] + bv1;
                }
            }
        }
    }
}

// ---------------- LSTM step: fused recurrent GEMM + pointwise ----------------
// Grid: 16 CTAs, each owns j in [j0, j0+32). Packed column p = jl*4 + q maps to
// gate row g = q*512 + j0 + jl of W_hh, so the CTA holds i,f,g,o for its j-slice
// and fuses the nonlinearity + c/h update. t==0: gates = xproj only (h0 = c0 = 0).
__global__ __launch_bounds__(256)
void lstm_step(const float* __restrict__ Whh, int t) {
    __shared__ float sm[8448];                 // max(64*36 + 128*36, 64*132)
    float* sA = sm;                            // [64][36]
    float* sB = sm + 64 * SROW;                // [128][36]
    float* sG = sm;                            // [64][132]  (aliased after mainloop)

    const int j0   = blockIdx.x * 32;
    const int tid  = threadIdx.x;
    const int warp = tid >> 5, lane = tid & 31;
    const int grp  = lane >> 2, tig = lane & 3;
    const int wm = warp & 3;                   // m16 tile: rows wm*16
    const int wn = warp >> 2;                  // p cols: wn*64

    if (t > 0) {
        float acc[8][4];
        #pragma unroll
        for (int nt = 0; nt < 8; nt++)
            #pragma unroll
            for (int q = 0; q < 4; q++) acc[nt][q] = 0.0f;

        const float* A = d_hs + (size_t)(t - 1) * BATCH * HIDDEN;
        for (int k0 = 0; k0 < HIDDEN; k0 += 32) {
            #pragma unroll
            for (int i = 0; i < 2; i++) {      // sA: 64x32
                int lin = tid + i * 256;       // 0..511
                int r = lin >> 3;
                int c4 = (lin & 7) << 2;
                float4 v = *(const float4*)(A + (size_t)r * HIDDEN + k0 + c4);
                float* da = sA + r * SROW + c4;
                da[0] = __uint_as_float(f2tf32(v.x));
                da[1] = __uint_as_float(f2tf32(v.y));
                da[2] = __uint_as_float(f2tf32(v.z));
                da[3] = __uint_as_float(f2tf32(v.w));
            }
            #pragma unroll
            for (int i = 0; i < 4; i++) {      // sB: 128 packed gate rows x 32
                int lin = tid + i * 256;       // 0..1023
                int p = lin >> 3;
                int c4 = (lin & 7) << 2;
                int g = (p & 3) * HIDDEN + j0 + (p >> 2);
                float4 v = *(const float4*)(Whh + (size_t)g * HIDDEN + k0 + c4);
                float* db = sB + p * SROW + c4;
                db[0] = __uint_as_float(f2tf32(v.x));
                db[1] = __uint_as_float(f2tf32(v.y));
                db[2] = __uint_as_float(f2tf32(v.z));
                db[3] = __uint_as_float(f2tf32(v.w));
            }
            __syncthreads();

            #pragma unroll
            for (int ks = 0; ks < 32; ks += 8) {
                unsigned af[4];
                const float* abase = sA + (wm * 16) * SROW + ks;
                af[0] = __float_as_uint(abase[grp * SROW + tig]);
                af[1] = __float_as_uint(abase[(grp + 8) * SROW + tig]);
                af[2] = __float_as_uint(abase[grp * SROW + tig + 4]);
                af[3] = __float_as_uint(abase[(grp + 8) * SROW + tig + 4]);
                #pragma unroll
                for (int nt = 0; nt < 8; nt++) {
                    unsigned bf[2];
                    const float* bbase = sB + (wn * 64 + nt * 8 + grp) * SROW + ks;
                    bf[0] = __float_as_uint(bbase[tig]);
                    bf[1] = __float_as_uint(bbase[tig + 4]);
                    mma_tf32(acc[nt], af, bf);
                }
            }
            __syncthreads();
        }

        // dump accumulators into sG[64][132] in packed-p column order
        #pragma unroll
        for (int nt = 0; nt < 8; nt++) {
            int r = wm * 16 + grp;
            int cc = wn * 64 + nt * 8 + 2 * tig;
            sG[r * 132 + cc]           = acc[nt][0];
            sG[r * 132 + cc + 1]       = acc[nt][1];
            sG[(r + 8) * 132 + cc]     = acc[nt][2];
            sG[(r + 8) * 132 + cc + 1] = acc[nt][3];
        }
        __syncthreads();
    }

    // pointwise: 64 batches x 32 j -> 8 per thread
    #pragma unroll
    for (int it = 0; it < 8; it++) {
        int id = tid + it * 256;               // 0..2047
        int jl = id & 31;
        int b  = id >> 5;
        int j  = j0 + jl;
        const float* xp = d_xproj + ((size_t)(t * BATCH + b)) * G4 + j;
        float gi = xp[0];
        float gf = xp[HIDDEN];
        float gg = xp[2 * HIDDEN];
        float go = xp[3 * HIDDEN];
        float cp = 0.0f;
        if (t > 0) {
            gi += sG[b * 132 + jl * 4 + 0];
            gf += sG[b * 132 + jl * 4 + 1];
            gg += sG[b * 132 + jl * 4 + 2];
            go += sG[b * 132 + jl * 4 + 3];
            cp  = d_c[b * HIDDEN + j];
        }
        float ii = sigf(gi);
        float ff = sigf(gf);
        float oo = sigf(go);
        float cn = ff * cp + ii * tanhf(gg);
        float hn = oo * tanhf(cn);
        d_c[b * HIDDEN + j] = cn;
        d_hs[((size_t)t * BATCH + b) * HIDDEN + j] = hn;
    }
}

// ---------------- launch ------------------------------------------------------
extern "C" void kernel_launch(void* const* d_in, const int* in_sizes, int n_in,
                              void* d_out, int out_size) {
    const float* features  = (const float*)d_in[0];
    const int*   captions  = (const int*)  d_in[1];
    /* lengths d_in[2] unused by the reference */
    const float* embedding = (const float*)d_in[3];
    const float* W_ih      = (const float*)d_in[4];
    const float* W_hh      = (const float*)d_in[5];
    const float* b_ih      = (const float*)d_in[6];
    const float* b_hh      = (const float*)d_in[7];
    const float* W_out     = (const float*)d_in[8];
    const float* b_out     = (const float*)d_in[9];
    float* out = (float*)d_out;

    float *xg_p, *xproj_p, *hs_p;
    cudaGetSymbolAddress((void**)&xg_p,    d_xg);
    cudaGetSymbolAddress((void**)&xproj_p, d_xproj);
    cudaGetSymbolAddress((void**)&hs_p,    d_hs);

    // 1) gather x rows (s-major: row = s*64 + b)
    gather_kernel<<<MROWS, 256>>>(features, captions, embedding);

    // 2) x_proj = x @ W_ih^T + b_ih + b_hh   [2112 x 2048], K=256
    {
        dim3 grid(G4 / 128, (MROWS + 127) / 128);
        gemm128<<<grid, 256>>>(xg_p, W_ih, b_ih, b_hh, xproj_p,
                               MROWS, G4, EMBED, 0);
    }

    // 3) 33 sequential LSTM steps
    for (int t = 0; t < SEQ; t++) {
        lstm_step<<<HIDDEN / 32, 256>>>(W_hh, t);
    }

    // 4) logits = hs @ W_out^T + b_out -> out[b][s][v]   [2112 x 32000], K=512
    {
        dim3 grid(VOCAB / 128, (MROWS + 127) / 128);
        gemm128<<<grid, 256>>>(hs_p, W_out, b_out, nullptr, out,
                               MROWS, VOCAB, HIDDEN, 1);
    }
}

// round 3
// speedup vs baseline: 1.6569x; 1.6569x over previous
#include <cuda_runtime.h>
#include <cstdint>

#define VOCAB  32000
#define EMBED  256
#define HIDDEN 512
#define BATCH  64
#define TCAP   32
#define SEQ    33                 // T_CAP + 1
#define MROWS  (SEQ*BATCH)        // 2112
#define G4     (4*HIDDEN)         // 2048
#define OUT_SV (SEQ*VOCAB)        // 1056000

#define NCTA   32                 // persistent LSTM CTAs
#define JW     16                 // hidden units per CTA
#define SW     516                // smem stride for W slice   (mod 32 == 4 -> conflict free)
#define SAW    68                 // smem stride for A chunks  (mod 32 == 4 -> conflict free)
// dynamic smem: W 64x516 + 2 * A 64x68 + G 64x68  (floats)
#define SMEM_FLOATS (64*SW + 3*64*SAW)
#define SMEM_BYTES  (SMEM_FLOATS * 4)

// ---------------- scratch (static device globals; no allocation) -------------
__device__ float d_xg[MROWS*EMBED];        // gathered inputs  [s*64+b][256]
__device__ float d_xproj[MROWS*G4];        // x@W_ih^T + b     [s*64+b][2048]
__device__ float d_hs[MROWS*HIDDEN];       // hidden states    [s*64+b][512]
__device__ unsigned d_bar[SEQ];            // per-step barrier counters

// ---------------- helpers ----------------------------------------------------
__device__ __forceinline__ unsigned f2tf32(float x) {
    unsigned r;
    asm("cvt.rna.tf32.f32 %0, %1;" : "=r"(r) : "f"(x));
    return r;
}

__device__ __forceinline__ void mma_tf32(float c[4], const unsigned a[4], const unsigned b[2]) {
    asm volatile(
        "mma.sync.aligned.m16n8k8.row.col.f32.tf32.tf32.f32 "
        "{%0,%1,%2,%3},{%4,%5,%6,%7},{%8,%9},{%0,%1,%2,%3};\n"
        : "+f"(c[0]), "+f"(c[1]), "+f"(c[2]), "+f"(c[3])
        : "r"(a[0]), "r"(a[1]), "r"(a[2]), "r"(a[3]), "r"(b[0]), "r"(b[1]));
}

__device__ __forceinline__ unsigned ld_acq(const unsigned* p) {
    unsigned v;
    asm volatile("ld.acquire.gpu.global.u32 %0, [%1];" : "=r"(v) : "l"(p));
    return v;
}

__device__ __forceinline__ float sigf(float x) { return 1.0f / (1.0f + expf(-x)); }

// ---------------- barrier reset (host-launched before persistent kernel) -----
__global__ void bar_reset() {
    if (threadIdx.x < SEQ) d_bar[threadIdx.x] = 0;
}

// ---------------- gather: build x rows (s-major) -----------------------------
__global__ void gather_kernel(const float* __restrict__ features,
                              const int*   __restrict__ captions,
                              const float* __restrict__ embedding) {
    int m = blockIdx.x;            // 0..2111
    int s = m >> 6, b = m & 63;
    const float* src = (s == 0) ? (features + (size_t)b * EMBED)
                                : (embedding + (size_t)captions[b * TCAP + (s - 1)] * EMBED);
    float* dst = d_xg + (size_t)m * EMBED;
    for (int i = threadIdx.x; i < EMBED; i += blockDim.x) dst[i] = src[i];
}

// ---------------- generic 128x128 tf32 GEMM: C = A[M,K] @ B[N,K]^T + bias ----
// mode 0: C[m*N+n] = acc + bias1[n] + bias2[n]          (x_proj)
// mode 1: out[b*OUT_SV + s*VOCAB + n] = acc + bias1[n]  (logits; m = s*64+b)
#define SROW 36
__global__ __launch_bounds__(256, 2)
void gemm128(const float* __restrict__ A, const float* __restrict__ B,
             const float* __restrict__ bias1, const float* __restrict__ bias2,
             float* __restrict__ C, int M, int N, int K, int mode) {
    __shared__ float sA[128 * SROW];
    __shared__ float sB[128 * SROW];

    const int m0 = blockIdx.y * 128, n0 = blockIdx.x * 128;
    const int tid  = threadIdx.x;
    const int warp = tid >> 5, lane = tid & 31;
    const int grp  = lane >> 2, tig = lane & 3;
    const int wm = warp & 1, wn = warp >> 1;       // 2 warps in M, 4 in N
    const int mb = wm * 64, nb = wn * 32;          // warp tile 64x32

    float acc[4][4][4];
    #pragma unroll
    for (int mt = 0; mt < 4; mt++)
        #pragma unroll
        for (int nt = 0; nt < 4; nt++)
            #pragma unroll
            for (int q = 0; q < 4; q++) acc[mt][nt][q] = 0.0f;

    for (int k0 = 0; k0 < K; k0 += 32) {
        #pragma unroll
        for (int i = 0; i < 4; i++) {
            int lin = tid + i * 256;               // 0..1023
            int r = lin >> 3;
            int c4 = (lin & 7) << 2;
            int gm = m0 + r;
            float4 va = (gm < M) ? *(const float4*)(A + (size_t)gm * K + k0 + c4)
                                 : make_float4(0.f, 0.f, 0.f, 0.f);
            float* da = sA + r * SROW + c4;
            da[0] = __uint_as_float(f2tf32(va.x));
            da[1] = __uint_as_float(f2tf32(va.y));
            da[2] = __uint_as_float(f2tf32(va.z));
            da[3] = __uint_as_float(f2tf32(va.w));
            float4 vb = *(const float4*)(B + (size_t)(n0 + r) * K + k0 + c4);
            float* db = sB + r * SROW + c4;
            db[0] = __uint_as_float(f2tf32(vb.x));
            db[1] = __uint_as_float(f2tf32(vb.y));
            db[2] = __uint_as_float(f2tf32(vb.z));
            db[3] = __uint_as_float(f2tf32(vb.w));
        }
        __syncthreads();

        #pragma unroll
        for (int ks = 0; ks < 32; ks += 8) {
            unsigned af[4][4];
            unsigned bf[4][2];
            #pragma unroll
            for (int mt = 0; mt < 4; mt++) {
                const float* base = sA + (mb + mt * 16) * SROW + ks;
                af[mt][0] = __float_as_uint(base[grp * SROW + tig]);
                af[mt][1] = __float_as_uint(base[(grp + 8) * SROW + tig]);
                af[mt][2] = __float_as_uint(base[grp * SROW + tig + 4]);
                af[mt][3] = __float_as_uint(base[(grp + 8) * SROW + tig + 4]);
            }
            #pragma unroll
            for (int nt = 0; nt < 4; nt++) {
                const float* base = sB + (nb + nt * 8 + grp) * SROW + ks;
                bf[nt][0] = __float_as_uint(base[tig]);
                bf[nt][1] = __float_as_uint(base[tig + 4]);
            }
            #pragma unroll
            for (int mt = 0; mt < 4; mt++)
                #pragma unroll
                for (int nt = 0; nt < 4; nt++)
                    mma_tf32(acc[mt][nt], af[mt], bf[nt]);
        }
        __syncthreads();
    }

    #pragma unroll
    for (int mt = 0; mt < 4; mt++) {
        #pragma unroll
        for (int nt = 0; nt < 4; nt++) {
            int rA = m0 + mb + mt * 16 + grp;
            int rB = rA + 8;
            int n  = n0 + nb + nt * 8 + 2 * tig;
            float bv0 = bias1 ? bias1[n]     : 0.0f;
            float bv1 = bias1 ? bias1[n + 1] : 0.0f;
            if (bias2) { bv0 += bias2[n]; bv1 += bias2[n + 1]; }
            if (mode == 0) {
                if (rA < M) {
                    C[(size_t)rA * N + n]     = acc[mt][nt][0] + bv0;
                    C[(size_t)rA * N + n + 1] = acc[mt][nt][1] + bv1;
                }
                if (rB < M) {
                    C[(size_t)rB * N + n]     = acc[mt][nt][2] + bv0;
                    C[(size_t)rB * N + n + 1] = acc[mt][nt][3] + bv1;
                }
            } else {
                if (rA < M) {
                    int s = rA >> 6, b = rA & 63;
                    size_t o = (size_t)b * OUT_SV + (size_t)s * VOCAB + n;
                    C[o]     = acc[mt][nt][0] + bv0;
                    C[o + 1] = acc[mt][nt][1] + bv1;
                }
                if (rB < M) {
                    int s = rB >> 6, b = rB & 63;
                    size_t o = (size_t)b * OUT_SV + (size_t)s * VOCAB + n;
                    C[o]     = acc[mt][nt][2] + bv0;
                    C[o + 1] = acc[mt][nt][3] + bv1;
                }
            }
        }
    }
}

// ---------------- persistent LSTM: all 33 steps in one launch ----------------
// 32 CTAs; CTA owns j in [j0, j0+16). Packed col p = jl*4+q  -> W_hh row
// g = q*512 + j0 + jl. W slice (64x512) staged to smem ONCE as tf32.
// Cell state lives in registers. Steps separated by a gpu-scope barrier.
extern __shared__ float smem_dyn[];

__global__ __launch_bounds__(256, 1)
void lstm_persist(const float* __restrict__ Whh) {
    float* sW  = smem_dyn;                 // [64][516]
    float* sA0 = sW  + 64 * SW;            // [64][68]
    float* sA1 = sA0 + 64 * SAW;           // [64][68]
    float* sG  = sA1 + 64 * SAW;           // [64][68]

    const int j0   = blockIdx.x * JW;
    const int tid  = threadIdx.x;
    const int warp = tid >> 5, lane = tid & 31;
    const int grp  = lane >> 2, tig = lane & 3;
    const int wm = warp & 3;               // m16 tile rows: wm*16
    const int wn = warp >> 2;              // packed cols:   wn*32 (4 n8 tiles)

    // ---- stage W_hh slice into smem (tf32), once ----
    for (int idx = tid; idx < 64 * 128; idx += 256) {
        int p  = idx >> 7;
        int c4 = (idx & 127) << 2;
        int g  = (p & 3) * HIDDEN + j0 + (p >> 2);
        float4 v = *(const float4*)(Whh + (size_t)g * HIDDEN + c4);
        float* dw = sW + p * SW + c4;
        dw[0] = __uint_as_float(f2tf32(v.x));
        dw[1] = __uint_as_float(f2tf32(v.y));
        dw[2] = __uint_as_float(f2tf32(v.z));
        dw[3] = __uint_as_float(f2tf32(v.w));
    }
    __syncthreads();

    float cst[4] = {0.f, 0.f, 0.f, 0.f};   // cell state, 4 (b,jl) items per thread

    for (int t = 0; t < SEQ; t++) {
        // prefetch this step's xproj gate biases (independent of h) early
        float pgi[4], pgf[4], pgg[4], pgo[4];
        #pragma unroll
        for (int it = 0; it < 4; it++) {
            int id = tid + it * 256;           // 0..1023
            int jl = id & 15, b = id >> 4;
            const float* xp = d_xproj + ((size_t)(t * BATCH + b)) * G4 + j0 + jl;
            pgi[it] = xp[0];
            pgf[it] = xp[HIDDEN];
            pgg[it] = xp[2 * HIDDEN];
            pgo[it] = xp[3 * HIDDEN];
        }

        if (t > 0) {
            const float* A = d_hs + (size_t)(t - 1) * BATCH * HIDDEN;
            float acc[4][4];
            #pragma unroll
            for (int nt = 0; nt < 4; nt++)
                #pragma unroll
                for (int q = 0; q < 4; q++) acc[nt][q] = 0.0f;

            // stage chunk 0 (64 x 64)
            #pragma unroll
            for (int i = 0; i < 4; i++) {
                int lin = tid + i * 256;
                int r = lin >> 4, c4 = (lin & 15) << 2;
                float4 v = *(const float4*)(A + (size_t)r * HIDDEN + c4);
                float* da = sA0 + r * SAW + c4;
                da[0] = __uint_as_float(f2tf32(v.x));
                da[1] = __uint_as_float(f2tf32(v.y));
                da[2] = __uint_as_float(f2tf32(v.z));
                da[3] = __uint_as_float(f2tf32(v.w));
            }
            __syncthreads();

            #pragma unroll
            for (int c = 0; c < 8; c++) {
                float* cur = (c & 1) ? sA1 : sA0;
                float* nxt = (c & 1) ? sA0 : sA1;
                float4 pre[4];
                if (c < 7) {
                    #pragma unroll
                    for (int i = 0; i < 4; i++) {
                        int lin = tid + i * 256;
                        int r = lin >> 4, c4 = (lin & 15) << 2;
                        pre[i] = *(const float4*)(A + (size_t)r * HIDDEN + (c + 1) * 64 + c4);
                    }
                }
                #pragma unroll
                for (int ks = 0; ks < 64; ks += 8) {
                    unsigned af[4];
                    const float* ab = cur + (wm * 16) * SAW + ks;
                    af[0] = __float_as_uint(ab[grp * SAW + tig]);
                    af[1] = __float_as_uint(ab[(grp + 8) * SAW + tig]);
                    af[2] = __float_as_uint(ab[grp * SAW + tig + 4]);
                    af[3] = __float_as_uint(ab[(grp + 8) * SAW + tig + 4]);
                    #pragma unroll
                    for (int nt = 0; nt < 4; nt++) {
                        unsigned bf[2];
                        const float* bb = sW + (wn * 32 + nt * 8 + grp) * SW + c * 64 + ks;
                        bf[0] = __float_as_uint(bb[tig]);
                        bf[1] = __float_as_uint(bb[tig + 4]);
                        mma_tf32(acc[nt], af, bf);
                    }
                }
                if (c < 7) {
                    #pragma unroll
                    for (int i = 0; i < 4; i++) {
                        int lin = tid + i * 256;
                        int r = lin >> 4, c4 = (lin & 15) << 2;
                        float* da = nxt + r * SAW + c4;
                        da[0] = __uint_as_float(f2tf32(pre[i].x));
                        da[1] = __uint_as_float(f2tf32(pre[i].y));
                        da[2] = __uint_as_float(f2tf32(pre[i].z));
                        da[3] = __uint_as_float(f2tf32(pre[i].w));
                    }
                }
                __syncthreads();
            }

            // dump accumulators into sG[64][68] in packed-p order
            #pragma unroll
            for (int nt = 0; nt < 4; nt++) {
                int r  = wm * 16 + grp;
                int cc = wn * 32 + nt * 8 + 2 * tig;
                sG[r * SAW + cc]           = acc[nt][0];
                sG[r * SAW + cc + 1]       = acc[nt][1];
                sG[(r + 8) * SAW + cc]     = acc[nt][2];
                sG[(r + 8) * SAW + cc + 1] = acc[nt][3];
            }
            __syncthreads();
        }

        // pointwise: 64 batches x 16 j -> 4 items per thread; c stays in regs
        #pragma unroll
        for (int it = 0; it < 4; it++) {
            int id = tid + it * 256;
            int jl = id & 15, b = id >> 4;
            int j  = j0 + jl;
            float gi = pgi[it], gf = pgf[it], gg = pgg[it], go = pgo[it];
            if (t > 0) {
                gi += sG[b * SAW + jl * 4 + 0];
                gf += sG[b * SAW + jl * 4 + 1];
                gg += sG[b * SAW + jl * 4 + 2];
                go += sG[b * SAW + jl * 4 + 3];
            }
            float cn = sigf(gf) * cst[it] + sigf(gi) * tanhf(gg);
            float hn = sigf(go) * tanhf(cn);
            cst[it] = cn;
            d_hs[((size_t)t * BATCH + b) * HIDDEN + j] = hn;
        }

        // gpu-scope step barrier (CG grid.sync pattern); none needed after last step
        if (t < SEQ - 1) {
            __syncthreads();
            if (tid == 0) {
                __threadfence();
                atomicAdd(&d_bar[t], 1u);
                while (ld_acq(&d_bar[t]) < NCTA) { }
            }
            __syncthreads();
        }
    }
}

// ---------------- launch ------------------------------------------------------
extern "C" void kernel_launch(void* const* d_in, const int* in_sizes, int n_in,
                              void* d_out, int out_size) {
    const float* features  = (const float*)d_in[0];
    const int*   captions  = (const int*)  d_in[1];
    /* lengths d_in[2] unused by the reference */
    const float* embedding = (const float*)d_in[3];
    const float* W_ih      = (const float*)d_in[4];
    const float* W_hh      = (const float*)d_in[5];
    const float* b_ih      = (const float*)d_in[6];
    const float* b_hh      = (const float*)d_in[7];
    const float* W_out     = (const float*)d_in[8];
    const float* b_out     = (const float*)d_in[9];
    float* out = (float*)d_out;

    float *xg_p, *xproj_p, *hs_p;
    cudaGetSymbolAddress((void**)&xg_p,    d_xg);
    cudaGetSymbolAddress((void**)&xproj_p, d_xproj);
    cudaGetSymbolAddress((void**)&hs_p,    d_hs);

    static bool attr_done = false;
    if (!attr_done) {
        cudaFuncSetAttribute(lstm_persist,
                             cudaFuncAttributeMaxDynamicSharedMemorySize, SMEM_BYTES);
        attr_done = true;
    }

    // 1) gather x rows (s-major: row = s*64 + b)
    gather_kernel<<<MROWS, 256>>>(features, captions, embedding);

    // 2) x_proj = x @ W_ih^T + b_ih + b_hh   [2112 x 2048], K=256
    {
        dim3 grid(G4 / 128, (MROWS + 127) / 128);
        gemm128<<<grid, 256>>>(xg_p, W_ih, b_ih, b_hh, xproj_p,
                               MROWS, G4, EMBED, 0);
    }

    // 3) all 33 LSTM steps in one persistent kernel
    bar_reset<<<1, 64>>>();
    lstm_persist<<<NCTA, 256, SMEM_BYTES>>>(W_hh);

    // 4) logits = hs @ W_out^T + b_out -> out[b][s][v]   [2112 x 32000], K=512
    {
        dim3 grid(VOCAB / 128, (MROWS + 127) / 128);
        gemm128<<<grid, 256>>>(hs_p, W_out, b_out, nullptr, out,
                               MROWS, VOCAB, HIDDEN, 1);
    }
}

// round 6
// speedup vs baseline: 2.0308x; 1.2257x over previous
#include <cuda_runtime.h>
#include <cstdint>

#define VOCAB  32000
#define EMBED  256
#define HIDDEN 512
#define BATCH  64
#define TCAP   32
#define SEQ    33                 // T_CAP + 1
#define MROWS  (SEQ*BATCH)        // 2112
#define MPAD   2176               // 17*128 (padded rows for un-guarded cp.async)
#define G4     (4*HIDDEN)         // 2048
#define OUT_SV (SEQ*VOCAB)        // 1056000

// ---- LSTM persistent config ----
#define NCTA   64                 // persistent LSTM CTAs
#define JW     8                  // hidden units per CTA
#define PR     32                 // packed gate rows per CTA (4*JW)
#define SHW    516                // smem stride (mod 32 == 4 -> conflict free)
#define LS_H   (PR*SHW)           // sH offset (floats)
#define LS_G   (LS_H + 64*SHW)    // sG offset
#define LS_TOT (LS_G + 64*36)     // total floats = 51840 (207,360 B)

// ---- GEMM config ----
#define SROW   36
#define GSTAGE (128*SROW)                 // floats per tile per stage
#define GEMM_SMEM_BYTES (4*GSTAGE*4)      // 2 stages x (A+B) = 73,728 B

// ---------------- scratch (static device globals; no allocation) -------------
__device__ float d_xg[MPAD*EMBED];         // gathered inputs (tf32-rounded), padded
__device__ float d_xproj[MROWS*G4];        // x@W_ih^T + b
__device__ float d_hs[MPAD*HIDDEN];        // hidden states (tf32-rounded), padded
__device__ float d_wih_r[G4*EMBED];        // tf32-rounded W_ih
__device__ float d_wout_r[VOCAB*HIDDEN];   // tf32-rounded W_out
__device__ unsigned d_bar[SEQ];            // per-step barrier counters

// ---------------- helpers ----------------------------------------------------
__device__ __forceinline__ unsigned f2tf32(float x) {
    unsigned r;
    asm("cvt.rna.tf32.f32 %0, %1;" : "=r"(r) : "f"(x));
    return r;
}
__device__ __forceinline__ float rtf(float x) { return __uint_as_float(f2tf32(x)); }

__device__ __forceinline__ void mma_tf32(float c[4], const unsigned a[4], const unsigned b[2]) {
    asm volatile(
        "mma.sync.aligned.m16n8k8.row.col.f32.tf32.tf32.f32 "
        "{%0,%1,%2,%3},{%4,%5,%6,%7},{%8,%9},{%0,%1,%2,%3};\n"
        : "+f"(c[0]), "+f"(c[1]), "+f"(c[2]), "+f"(c[3])
        : "r"(a[0]), "r"(a[1]), "r"(a[2]), "r"(a[3]), "r"(b[0]), "r"(b[1]));
}

__device__ __forceinline__ unsigned smem_u32(const void* p) {
    return (unsigned)__cvta_generic_to_shared(p);
}
__device__ __forceinline__ void cp16(unsigned dst, const void* src) {
    asm volatile("cp.async.cg.shared.global [%0], [%1], 16;" :: "r"(dst), "l"(src));
}
#define CP_COMMIT() asm volatile("cp.async.commit_group;")
#define CP_WAIT(n)  asm volatile("cp.async.wait_group %0;" :: "n"(n))

__device__ __forceinline__ unsigned ld_acq(const unsigned* p) {
    unsigned v;
    asm volatile("ld.acquire.gpu.global.u32 %0, [%1];" : "=r"(v) : "l"(p));
    return v;
}
__device__ __forceinline__ float sigf(float x) { return 1.0f / (1.0f + expf(-x)); }

// ---------------- small prep kernels -----------------------------------------
__global__ void bar_reset() {
    if (threadIdx.x < SEQ) d_bar[threadIdx.x] = 0;
}

__global__ void round4(const float* __restrict__ src, float* __restrict__ dst, int n4) {
    int i = blockIdx.x * blockDim.x + threadIdx.x;
    if (i < n4) {
        float4 v = ((const float4*)src)[i];
        v.x = rtf(v.x); v.y = rtf(v.y); v.z = rtf(v.z); v.w = rtf(v.w);
        ((float4*)dst)[i] = v;
    }
}

// gather x rows (s-major: row = s*64 + b), tf32-rounded
__global__ void gather_kernel(const float* __restrict__ features,
                              const int*   __restrict__ captions,
                              const float* __restrict__ embedding) {
    int m = blockIdx.x;            // 0..2111
    int s = m >> 6, b = m & 63;
    const float* src = (s == 0) ? (features + (size_t)b * EMBED)
                                : (embedding + (size_t)captions[b * TCAP + (s - 1)] * EMBED);
    float* dst = d_xg + (size_t)m * EMBED;
    for (int i = threadIdx.x; i < EMBED; i += blockDim.x) dst[i] = rtf(src[i]);
}

// ------- 128x128 tf32 GEMM, 2-stage cp.async pipeline: C = A @ B^T + bias ----
// Inputs MUST be pre-rounded to tf32 values. A padded to grid.y*128 rows.
// mode 0: C[m*N+n] = acc + bias1[n] + bias2[n]          (x_proj)
// mode 1: out[b*OUT_SV + s*VOCAB + n] = acc + bias1[n]  (logits; m = s*64+b)
__global__ __launch_bounds__(256, 2)
void gemm_tf32(const float* __restrict__ A, const float* __restrict__ B,
               const float* __restrict__ bias1, const float* __restrict__ bias2,
               float* __restrict__ C, int M, int N, int K, int mode) {
    extern __shared__ float sm[];
    const unsigned smu = smem_u32(sm);

    const int m0 = blockIdx.y * 128, n0 = blockIdx.x * 128;
    const int tid  = threadIdx.x;
    const int warp = tid >> 5, lane = tid & 31;
    const int grp  = lane >> 2, tig = lane & 3;
    const int wm = warp & 1, wn = warp >> 1;       // 2 warps in M, 4 in N
    const int mb = wm * 64, nb = wn * 32;          // warp tile 64x32

    float acc[4][4][4];
    #pragma unroll
    for (int mt = 0; mt < 4; mt++)
        #pragma unroll
        for (int nt = 0; nt < 4; nt++)
            #pragma unroll
            for (int q = 0; q < 4; q++) acc[mt][nt][q] = 0.0f;

    const int r_st   = tid >> 3;            // staging row this thread handles (+0,+32,..)
    const int c16_st = tid & 7;             // 16B-chunk within 32-float row

    auto stage = [&](int buf, int k0) {
        unsigned base = smu + (unsigned)buf * 2 * GSTAGE * 4;
        #pragma unroll
        for (int i = 0; i < 4; i++) {
            int r = r_st + i * 32;
            unsigned off = (unsigned)(r * SROW + c16_st * 4) * 4;
            cp16(base + off,              A + (size_t)(m0 + r) * K + k0 + c16_st * 4);
            cp16(base + GSTAGE * 4 + off, B + (size_t)(n0 + r) * K + k0 + c16_st * 4);
        }
    };

    const int nk = K >> 5;
    stage(0, 0); CP_COMMIT();
    int cur = 0;

    for (int kc = 0; kc < nk; kc++) {
        if (kc + 1 < nk) { stage(cur ^ 1, (kc + 1) * 32); CP_COMMIT(); CP_WAIT(1); }
        else             { CP_WAIT(0); }
        __syncthreads();

        const float* cA = sm + cur * 2 * GSTAGE;
        const float* cB = cA + GSTAGE;
        #pragma unroll
        for (int ks = 0; ks < 32; ks += 8) {
            unsigned af[4][4];
            unsigned bf[4][2];
            #pragma unroll
            for (int mt = 0; mt < 4; mt++) {
                const float* base = cA + (mb + mt * 16) * SROW + ks;
                af[mt][0] = __float_as_uint(base[grp * SROW + tig]);
                af[mt][1] = __float_as_uint(base[(grp + 8) * SROW + tig]);
                af[mt][2] = __float_as_uint(base[grp * SROW + tig + 4]);
                af[mt][3] = __float_as_uint(base[(grp + 8) * SROW + tig + 4]);
            }
            #pragma unroll
            for (int nt = 0; nt < 4; nt++) {
                const float* base = cB + (nb + nt * 8 + grp) * SROW + ks;
                bf[nt][0] = __float_as_uint(base[tig]);
                bf[nt][1] = __float_as_uint(base[tig + 4]);
            }
            #pragma unroll
            for (int mt = 0; mt < 4; mt++)
                #pragma unroll
                for (int nt = 0; nt < 4; nt++)
                    mma_tf32(acc[mt][nt], af[mt], bf[nt]);
        }
        __syncthreads();
        cur ^= 1;
    }

    // epilogue
    #pragma unroll
    for (int mt = 0; mt < 4; mt++) {
        #pragma unroll
        for (int nt = 0; nt < 4; nt++) {
            int rA = m0 + mb + mt * 16 + grp;
            int rB = rA + 8;
            int n  = n0 + nb + nt * 8 + 2 * tig;
            float bv0 = bias1 ? bias1[n]     : 0.0f;
            float bv1 = bias1 ? bias1[n + 1] : 0.0f;
            if (bias2) { bv0 += bias2[n]; bv1 += bias2[n + 1]; }
            if (mode == 0) {
                if (rA < M) {
                    C[(size_t)rA * N + n]     = acc[mt][nt][0] + bv0;
                    C[(size_t)rA * N + n + 1] = acc[mt][nt][1] + bv1;
                }
                if (rB < M) {
                    C[(size_t)rB * N + n]     = acc[mt][nt][2] + bv0;
                    C[(size_t)rB * N + n + 1] = acc[mt][nt][3] + bv1;
                }
            } else {
                if (rA < M) {
                    int s = rA >> 6, b = rA & 63;
                    size_t o = (size_t)b * OUT_SV + (size_t)s * VOCAB + n;
                    C[o]     = acc[mt][nt][0] + bv0;
                    C[o + 1] = acc[mt][nt][1] + bv1;
                }
                if (rB < M) {
                    int s = rB >> 6, b = rB & 63;
                    size_t o = (size_t)b * OUT_SV + (size_t)s * VOCAB + n;
                    C[o]     = acc[mt][nt][2] + bv0;
                    C[o + 1] = acc[mt][nt][3] + bv1;
                }
            }
        }
    }
}

// ---------------- persistent LSTM: all 33 steps in one launch ----------------
// 64 CTAs; CTA owns j in [j0, j0+8). Packed col p = jl*4+q -> W_hh row
// g = q*512 + j0 + jl. W slice (32x512) staged to smem once (tf32).
// Whole h_{t-1} (64x512) staged per step via cp.async in 2 halves.
__global__ __launch_bounds__(256, 1)
void lstm_persist(const float* __restrict__ Whh) {
    extern __shared__ float sm[];
    float* sW = sm;                 // [32][516]
    float* sH = sm + LS_H;          // [64][516]
    float* sG = sm + LS_G;          // [64][36]
    const unsigned smu = smem_u32(sm);

    const int j0   = blockIdx.x * JW;
    const int tid  = threadIdx.x;
    const int warp = tid >> 5, lane = tid & 31;
    const int grp  = lane >> 2, tig = lane & 3;
    const int wm = warp & 3;        // m16 tile rows: wm*16
    const int wn = warp >> 2;       // packed cols:   wn*16 (2 n8 tiles)

    // ---- stage W_hh slice into smem (tf32), once ----
    for (int idx = tid; idx < PR * 128; idx += 256) {
        int p  = idx >> 7;
        int c4 = (idx & 127) << 2;
        int g  = (p & 3) * HIDDEN + j0 + (p >> 2);
        float4 v = *(const float4*)(Whh + (size_t)g * HIDDEN + c4);
        float* dw = sW + p * SHW + c4;
        dw[0] = rtf(v.x); dw[1] = rtf(v.y); dw[2] = rtf(v.z); dw[3] = rtf(v.w);
    }
    __syncthreads();

    float cst[2] = {0.f, 0.f};      // cell state: 2 (b,jl) items per thread

    #pragma unroll 1
    for (int t = 0; t < SEQ; t++) {
        // prefetch this step's xproj gate biases (independent of h) early
        float pg[2][4];
        #pragma unroll
        for (int it = 0; it < 2; it++) {
            int id = tid + it * 256;           // 0..511
            int jl = id & 7, b = id >> 3;
            const float* xp = d_xproj + ((size_t)(t * BATCH + b)) * G4 + j0 + jl;
            pg[it][0] = xp[0];
            pg[it][1] = xp[HIDDEN];
            pg[it][2] = xp[2 * HIDDEN];
            pg[it][3] = xp[3 * HIDDEN];
        }

        float acc[2][4];
        #pragma unroll
        for (int nt = 0; nt < 2; nt++)
            #pragma unroll
            for (int q = 0; q < 4; q++) acc[nt][q] = 0.0f;

        if (t > 0) {
            const float* A = d_hs + (size_t)(t - 1) * BATCH * HIDDEN;
            // stage full h tile (64x512) in two halves (cp.async groups)
            const int r_st = tid >> 2, c16_st = tid & 3;   // 64 rows x 4 chunks/thread-row
            #pragma unroll
            for (int half = 0; half < 2; half++) {
                #pragma unroll
                for (int i = 0; i < 16; i++) {
                    int lin = tid + i * 256;               // 0..4095
                    int r = lin >> 6, c16 = lin & 63;
                    unsigned dst = smu + (unsigned)(LS_H + r * SHW + half * 256 + c16 * 4) * 4;
                    cp16(dst, A + (size_t)r * HIDDEN + half * 256 + c16 * 4);
                }
                CP_COMMIT();
            }
            (void)r_st; (void)c16_st;

            auto mma_half = [&](int half) {
                const int hk = half * 256;
                #pragma unroll
                for (int ks = 0; ks < 256; ks += 8) {
                    unsigned af[4];
                    const float* ab = sH + (wm * 16) * SHW + hk + ks;
                    af[0] = __float_as_uint(ab[grp * SHW + tig]);
                    af[1] = __float_as_uint(ab[(grp + 8) * SHW + tig]);
                    af[2] = __float_as_uint(ab[grp * SHW + tig + 4]);
                    af[3] = __float_as_uint(ab[(grp + 8) * SHW + tig + 4]);
                    #pragma unroll
                    for (int nt = 0; nt < 2; nt++) {
                        unsigned bf[2];
                        const float* bb = sW + (wn * 16 + nt * 8 + grp) * SHW + hk + ks;
                        bf[0] = __float_as_uint(bb[tig]);
                        bf[1] = __float_as_uint(bb[tig + 4]);
                        mma_tf32(acc[nt], af, bf);
                    }
                }
            };

            CP_WAIT(1); __syncthreads();
            mma_half(0);
            CP_WAIT(0); __syncthreads();
            mma_half(1);

            // dump accumulators into sG[64][36] in packed-p order
            __syncthreads();
            #pragma unroll
            for (int nt = 0; nt < 2; nt++) {
                int r  = wm * 16 + grp;
                int cc = wn * 16 + nt * 8 + 2 * tig;
                sG[r * 36 + cc]           = acc[nt][0];
                sG[r * 36 + cc + 1]       = acc[nt][1];
                sG[(r + 8) * 36 + cc]     = acc[nt][2];
                sG[(r + 8) * 36 + cc + 1] = acc[nt][3];
            }
            __syncthreads();
        }

        // pointwise: 64 batches x 8 j -> 2 items per thread; c stays in regs
        #pragma unroll
        for (int it = 0; it < 2; it++) {
            int id = tid + it * 256;
            int jl = id & 7, b = id >> 3;
            int j  = j0 + jl;
            float gi = pg[it][0], gf = pg[it][1], gg = pg[it][2], go = pg[it][3];
            if (t > 0) {
                gi += sG[b * 36 + jl * 4 + 0];
                gf += sG[b * 36 + jl * 4 + 1];
                gg += sG[b * 36 + jl * 4 + 2];
                go += sG[b * 36 + jl * 4 + 3];
            }
            float cn = sigf(gf) * cst[it] + sigf(gi) * tanhf(gg);
            float hn = sigf(go) * tanhf(cn);
            cst[it] = cn;
            d_hs[((size_t)t * BATCH + b) * HIDDEN + j] = rtf(hn);
        }

        // gpu-scope step barrier
        if (t < SEQ - 1) {
            __syncthreads();
            if (tid == 0) {
                __threadfence();
                atomicAdd(&d_bar[t], 1u);
                while (ld_acq(&d_bar[t]) < NCTA) { }
            }
            __syncthreads();
        }
    }
}

// ---------------- launch ------------------------------------------------------
extern "C" void kernel_launch(void* const* d_in, const int* in_sizes, int n_in,
                              void* d_out, int out_size) {
    const float* features  = (const float*)d_in[0];
    const int*   captions  = (const int*)  d_in[1];
    /* lengths d_in[2] unused by the reference */
    const float* embedding = (const float*)d_in[3];
    const float* W_ih      = (const float*)d_in[4];
    const float* W_hh      = (const float*)d_in[5];
    const float* b_ih      = (const float*)d_in[6];
    const float* b_hh      = (const float*)d_in[7];
    const float* W_out     = (const float*)d_in[8];
    const float* b_out     = (const float*)d_in[9];
    float* out = (float*)d_out;

    float *xg_p, *xproj_p, *hs_p, *wih_p, *wout_p;
    cudaGetSymbolAddress((void**)&xg_p,    d_xg);
    cudaGetSymbolAddress((void**)&xproj_p, d_xproj);
    cudaGetSymbolAddress((void**)&hs_p,    d_hs);
    cudaGetSymbolAddress((void**)&wih_p,   d_wih_r);
    cudaGetSymbolAddress((void**)&wout_p,  d_wout_r);

    cudaFuncSetAttribute(gemm_tf32,
                         cudaFuncAttributeMaxDynamicSharedMemorySize, GEMM_SMEM_BYTES);
    cudaFuncSetAttribute(lstm_persist,
                         cudaFuncAttributeMaxDynamicSharedMemorySize, LS_TOT * 4);

    // 1) gather x rows (tf32-rounded) + pre-round weights
    gather_kernel<<<MROWS, 256>>>(features, captions, embedding);
    round4<<<(G4 * EMBED / 4 + 255) / 256, 256>>>(W_ih, wih_p, G4 * EMBED / 4);
    round4<<<(VOCAB * HIDDEN / 4 + 255) / 256, 256>>>(W_out, wout_p, VOCAB * HIDDEN / 4);

    // 2) x_proj = x @ W_ih^T + b_ih + b_hh   [2112 x 2048], K=256
    {
        dim3 grid(G4 / 128, MPAD / 128);
        gemm_tf32<<<grid, 256, GEMM_SMEM_BYTES>>>(xg_p, wih_p, b_ih, b_hh, xproj_p,
                                                  MROWS, G4, EMBED, 0);
    }

    // 3) all 33 LSTM steps in one persistent kernel
    bar_reset<<<1, 64>>>();
    lstm_persist<<<NCTA, 256, LS_TOT * 4>>>(W_hh);

    // 4) logits = hs @ W_out^T + b_out -> out[b][s][v]   [2112 x 32000], K=512
    {
        dim3 grid(VOCAB / 128, MPAD / 128);
        gemm_tf32<<<grid, 256, GEMM_SMEM_BYTES>>>(hs_p, wout_p, b_out, nullptr, out,
                                                  MROWS, VOCAB, HIDDEN, 1);
    }
}